// round 14
// baseline (speedup 1.0000x reference)
#include <cuda_runtime.h>
#include <cuda_fp16.h>
#include <math.h>

#define BB 4
#define NN 50000
#define EE 800000
#define CC 128
#define ROWS_TOT 200000
#define ROWS_PAD 200064            // 1563 * 128
#define NTILES_MMA 1563
#define MINV (1.0f/200000.0f)

__device__ float g_X  [(size_t)ROWS_TOT * CC];
__device__ float g_A  [(size_t)ROWS_TOT * CC];
__device__ uint4 g_Ah [(size_t)ROWS_PAD * 16];          // pads stay zero (module init)
__device__ uint4 g_LXh[(size_t)ROWS_PAD * 16];          // pads stay zero (module init)
__device__ int2  g_csr[(size_t)BB * EE];
__device__ int   g_rowptr[BB * (NN + 1)];
__device__ int   g_cnt[ROWS_TOT];                       // zero at load; re-zeroed by k_scatter
__device__ int   g_cursor[ROWS_TOT];
__device__ float g_stats_a[11 * 256];                   // zero at load; re-zeroed by k_fold
__device__ float g_stats_l[10 * 256];
__device__ unsigned int g_Wh32[128 * 128];
__device__ unsigned int g_Wl32[128 * 128];
__device__ float g_bf[8 * 128];
__device__ float g_Wf2[128 * 128];
__device__ float g_bf2[4 * 128];

__device__ __forceinline__ float eluf(float v) { return v > 0.f ? v : expm1f(v); }
__device__ __forceinline__ void mma_f16(float* d, const unsigned int* a,
                                        unsigned int b0, unsigned int b1) {
    asm volatile(
        "mma.sync.aligned.m16n8k16.row.col.f32.f16.f16.f32 "
        "{%0,%1,%2,%3}, {%4,%5,%6,%7}, {%8,%9}, {%0,%1,%2,%3};"
        : "+f"(d[0]), "+f"(d[1]), "+f"(d[2]), "+f"(d[3])
        : "r"(a[0]), "r"(a[1]), "r"(a[2]), "r"(a[3]), "r"(b0), "r"(b1));
}
__device__ __forceinline__ void ldsm_x4(unsigned int* r, unsigned int addr) {
    asm volatile("ldmatrix.sync.aligned.m8n8.x4.shared.b16 {%0,%1,%2,%3}, [%4];"
        : "=r"(r[0]), "=r"(r[1]), "=r"(r[2]), "=r"(r[3]) : "r"(addr));
}
// fma 8 halves (uint4) * scalar into 8 fp32 accumulators
__device__ __forceinline__ void fma8h(float* a, uint4 w, float v) {
    const __half2* h = reinterpret_cast<const __half2*>(&w);
    #pragma unroll
    for (int j = 0; j < 4; j++) {
        float2 f = __half22float2(h[j]);
        a[2*j]   += f.x * v;
        a[2*j+1] += f.y * v;
    }
}
__device__ __forceinline__ uint4 pack8h(const float* a) {
    uint4 u;
    __half2* h = reinterpret_cast<__half2*>(&u);
    #pragma unroll
    for (int j = 0; j < 4; j++) h[j] = __floats2half2_rn(a[2*j], a[2*j+1]);
    return u;
}

// ---------------- fused input projection + edge histogram ----------------
#define IP_BLOCKS 1024
#define HIST_BLOCKS 2048
__global__ __launch_bounds__(256) void k_inproj_hist(
    const float* __restrict__ inputs, const float* __restrict__ noise,
    const float* __restrict__ Win, const float* __restrict__ bin,
    const float* __restrict__ Wn, const float* __restrict__ bn,
    float* __restrict__ X, __half* __restrict__ Ah, float* __restrict__ stats,
    const int* __restrict__ L_rows, int* __restrict__ cnt)
{
    int tid = threadIdx.x;
    if (blockIdx.x >= IP_BLOCKS) {
        int stride = HIST_BLOCKS * 256;
        for (int t = (blockIdx.x - IP_BLOCKS) * 256 + tid; t < BB * EE; t += stride) {
            int b = t / EE;
            atomicAdd(&cnt[b * NN + L_rows[t]], 1);
        }
        return;
    }
    __shared__ float sU[8][104];
    int half = tid >> 7;
    int t128 = tid & 127;
    float bias = bin[t128] + bn[t128];
    float psum = 0.f, psq = 0.f;
    for (int base = blockIdx.x * 8; base < ROWS_TOT; base += IP_BLOCKS * 8) {
        __syncthreads();
        for (int idx = tid; idx < 8 * 103; idx += 256) {
            int r = idx / 103, k = idx - r * 103;
            int row = base + r;
            sU[r][k] = (k < 100) ? noise[(size_t)row * 100 + k]
                                 : inputs[(size_t)row * 3 + (k - 100)];
        }
        __syncthreads();
        int r0 = half * 4;
        float acc0 = bias, acc1 = bias, acc2 = bias, acc3 = bias;
        #pragma unroll 5
        for (int kq = 0; kq < 25; kq++) {
            int k = kq * 4;
            float w0 = __ldg(&Wn[(k + 0) * 128 + t128]);
            float w1 = __ldg(&Wn[(k + 1) * 128 + t128]);
            float w2 = __ldg(&Wn[(k + 2) * 128 + t128]);
            float w3 = __ldg(&Wn[(k + 3) * 128 + t128]);
            float4 u0 = *reinterpret_cast<const float4*>(&sU[r0 + 0][k]);
            float4 u1 = *reinterpret_cast<const float4*>(&sU[r0 + 1][k]);
            float4 u2 = *reinterpret_cast<const float4*>(&sU[r0 + 2][k]);
            float4 u3 = *reinterpret_cast<const float4*>(&sU[r0 + 3][k]);
            acc0 += u0.x * w0 + u0.y * w1 + u0.z * w2 + u0.w * w3;
            acc1 += u1.x * w0 + u1.y * w1 + u1.z * w2 + u1.w * w3;
            acc2 += u2.x * w0 + u2.y * w1 + u2.z * w2 + u2.w * w3;
            acc3 += u3.x * w0 + u3.y * w1 + u3.z * w2 + u3.w * w3;
        }
        #pragma unroll
        for (int k = 0; k < 3; k++) {
            float w = __ldg(&Win[k * 128 + t128]);
            acc0 += sU[r0 + 0][100 + k] * w;
            acc1 += sU[r0 + 1][100 + k] * w;
            acc2 += sU[r0 + 2][100 + k] * w;
            acc3 += sU[r0 + 3][100 + k] * w;
        }
        float accs[4] = {acc0, acc1, acc2, acc3};
        #pragma unroll
        for (int r = 0; r < 4; r++) {
            int row = base + r0 + r;
            float v = accs[r];
            X[(size_t)row * CC + t128] = v;
            float e = eluf(v);
            Ah[(size_t)row * CC + t128] = __float2half_rn(e);
            psum += e; psq += e * e;
        }
    }
    atomicAdd(&stats[t128], psum);
    atomicAdd(&stats[128 + t128], psq);
}

__global__ void k_scan(const int* __restrict__ cnt, int* rowptr, int* cursor) {
    __shared__ int sh[1024];
    int b = blockIdx.x, tid = threadIdx.x;
    const int CH = 49;
    int start = tid * CH;
    int end = min(start + CH, NN);
    int s = 0;
    for (int i = start; i < end; i++) s += cnt[b * NN + i];
    sh[tid] = s;
    __syncthreads();
    for (int off = 1; off < 1024; off <<= 1) {
        int t = (tid >= off) ? sh[tid - off] : 0;
        __syncthreads();
        sh[tid] += t;
        __syncthreads();
    }
    int run = (tid == 0) ? 0 : sh[tid - 1];
    for (int i = start; i < end; i++) {
        rowptr[b * (NN + 1) + i] = run;
        cursor[b * NN + i] = run;
        run += cnt[b * NN + i];
    }
    if (tid == 1023) rowptr[b * (NN + 1) + NN] = run;
}

__global__ void k_scatter(const int* __restrict__ L_rows, const int* __restrict__ L_cols,
                          const float* __restrict__ L_vals, int* cursor, int2* csr,
                          int* cnt) {
    int stride = gridDim.x * blockDim.x;
    int t0 = blockIdx.x * blockDim.x + threadIdx.x;
    for (int i = t0; i < ROWS_TOT; i += stride) cnt[i] = 0;
    for (int t = t0; t < BB * EE; t += stride) {
        int b = t / EE;
        int r = L_rows[t];
        int pos = atomicAdd(&cursor[b * NN + r], 1);
        int2 e; e.x = L_cols[t]; e.y = __float_as_int(L_vals[t]);
        csr[(size_t)b * EE + pos] = e;
    }
}

// ---------------- CSR SpMM: 2 rows/warp, uint4 fp16 gather, MLP=4 ----------------
__global__ __launch_bounds__(256) void k_spmm(
    const uint4* __restrict__ Ah, const int* __restrict__ rowptr,
    const int2* __restrict__ csr, uint4* __restrict__ LXh, float* __restrict__ stats)
{
    __shared__ float s_sum[128], s_sq[128];
    int tid = threadIdx.x;
    if (tid < 128) { s_sum[tid] = 0.f; s_sq[tid] = 0.f; }
    __syncthreads();
    int warp = tid >> 5, lane = tid & 31;
    int half = lane >> 4, c16 = lane & 15;
    float psum[8], psq[8];
    #pragma unroll
    for (int j = 0; j < 8; j++) { psum[j] = 0.f; psq[j] = 0.f; }
    for (int g = blockIdx.x * 16 + warp * 2 + half; g < ROWS_TOT; g += gridDim.x * 16) {
        int b = g / NN;
        int i = g - b * NN;
        int p0 = rowptr[b * (NN + 1) + i];
        int p1 = rowptr[b * (NN + 1) + i + 1];
        const int2* ev = csr + (size_t)b * EE;
        const uint4* Ab = Ah + (size_t)b * NN * 16;
        float a0[8], a1[8], a2[8], a3[8];
        #pragma unroll
        for (int j = 0; j < 8; j++) { a0[j]=0.f; a1[j]=0.f; a2[j]=0.f; a3[j]=0.f; }
        int p = p0;
        for (; p + 4 <= p1; p += 4) {
            int2 e0 = __ldg(&ev[p + 0]);
            int2 e1 = __ldg(&ev[p + 1]);
            int2 e2 = __ldg(&ev[p + 2]);
            int2 e3 = __ldg(&ev[p + 3]);
            uint4 w0 = __ldg(Ab + (size_t)e0.x * 16 + c16);
            uint4 w1 = __ldg(Ab + (size_t)e1.x * 16 + c16);
            uint4 w2 = __ldg(Ab + (size_t)e2.x * 16 + c16);
            uint4 w3 = __ldg(Ab + (size_t)e3.x * 16 + c16);
            fma8h(a0, w0, __int_as_float(e0.y));
            fma8h(a1, w1, __int_as_float(e1.y));
            fma8h(a2, w2, __int_as_float(e2.y));
            fma8h(a3, w3, __int_as_float(e3.y));
        }
        for (; p < p1; p++) {
            int2 e = __ldg(&ev[p]);
            fma8h(a0, __ldg(Ab + (size_t)e.x * 16 + c16), __int_as_float(e.y));
        }
        float acc[8];
        #pragma unroll
        for (int j = 0; j < 8; j++) {
            acc[j] = (a0[j] + a1[j]) + (a2[j] + a3[j]);
            psum[j] += acc[j];
            psq[j]  += acc[j] * acc[j];
        }
        LXh[(size_t)g * 16 + c16] = pack8h(acc);
    }
    #pragma unroll
    for (int j = 0; j < 8; j++) {
        atomicAdd(&s_sum[c16 * 8 + j], psum[j]);
        atomicAdd(&s_sq [c16 * 8 + j], psq[j]);
    }
    __syncthreads();
    if (tid < 128) {
        atomicAdd(&stats[tid], s_sum[tid]);
        atomicAdd(&stats[128 + tid], s_sq[tid]);
    }
}

__global__ __launch_bounds__(128) void k_fold(
    float* __restrict__ sa, float* __restrict__ sl,
    const float* __restrict__ gamma, const float* __restrict__ beta,
    const float* __restrict__ W, const float* __restrict__ b,
    unsigned int* __restrict__ Wh32, unsigned int* __restrict__ Wl32,
    float* __restrict__ Wf2, float* bfp)
{
    __shared__ float s_scale[32], s_shift[32];
    int bi = blockIdx.x;
    int tid = threadIdx.x;
    if (tid < 32) {
        int c = bi * 32 + tid;
        float sum, sq;
        if (c < 128) { sum = sa[c]; sq = sa[128 + c]; }
        else         { sum = sl[c - 128]; sq = sl[c]; }
        float m = sum * MINV;
        float var = sq * MINV - m * m;
        float r = rsqrtf(var + 1e-5f);
        float sc = gamma[c] * r;
        s_scale[tid] = sc;
        s_shift[tid] = beta[c] - m * sc;
        if (c < 128) { sa[c] = 0.f; sa[128 + c] = 0.f; }
        else         { sl[c - 128] = 0.f; sl[c] = 0.f; }
    }
    __syncthreads();
    float bias = (bi == 0) ? b[tid] : 0.f;
    #pragma unroll 4
    for (int j = 0; j < 32; j += 2) {
        int c0 = bi * 32 + j;
        float w0r = W[c0 * 128 + tid];
        float w1r = W[(c0 + 1) * 128 + tid];
        float w0 = w0r * s_scale[j];
        float w1 = w1r * s_scale[j + 1];
        bias += s_shift[j] * w0r + s_shift[j + 1] * w1r;
        if (Wh32) {
            __half h0 = __float2half_rn(w0);
            __half h1 = __float2half_rn(w1);
            float l0 = w0 - __half2float(h0);
            float l1 = w1 - __half2float(h1);
            __half2 hw = __halves2half2(h0, h1);
            __half2 lw = __floats2half2_rn(l0, l1);
            Wh32[tid * 128 + (c0 >> 1)] = *reinterpret_cast<unsigned int*>(&hw);
            Wl32[tid * 128 + (c0 >> 1)] = *reinterpret_cast<unsigned int*>(&lw);
        } else {
            Wf2[c0 * 128 + tid] = w0;
            Wf2[(c0 + 1) * 128 + tid] = w1;
        }
    }
    bfp[bi * 128 + tid] = bias;
}

// ---------------- main GEMM: fp16 MMA, ldmatrix fragment loads, 2 CTAs/SM ----------------
__global__ __launch_bounds__(256, 2) void k_gemm_mma(
    const uint4* __restrict__ Ahin, const uint4* __restrict__ LXh,
    const unsigned int* __restrict__ Wh32, const unsigned int* __restrict__ Wl32,
    const float* __restrict__ bfp, const float* __restrict__ res, int has_res,
    float* __restrict__ xout, int store_x,
    float* __restrict__ Aout, int store_a,
    __half2* __restrict__ Ahout, float* __restrict__ stats)
{
    extern __shared__ unsigned int sm[];
    unsigned int* sWh = sm;              // 8192 words: [n][o^sw], current kc half
    unsigned int* sWl = sm + 8192;
    unsigned int* sA  = sm + 16384;      // 8192: 128 rows x 64 kpairs
    float* sBias = (float*)(sm + 24576);

    int tid = threadIdx.x, warp = tid >> 5, lane = tid & 31;
    int wm = warp >> 2, wn = warp & 3;
    int g = lane >> 2, t2 = lane & 3;

    if (tid < 128) {
        float bsum = 0.f;
        #pragma unroll
        for (int j = 0; j < 8; j++) bsum += bfp[j * 128 + tid];
        sBias[tid] = bsum;
    }
    float stS[4][2], stQ[4][2];
    #pragma unroll
    for (int i = 0; i < 4; i++) { stS[i][0]=0.f; stS[i][1]=0.f; stQ[i][0]=0.f; stQ[i][1]=0.f; }

    // ldmatrix lane decomposition
    int mq = lane >> 3, rq = lane & 7;
    int swq = rq << 2;
    unsigned int sA_u  = (unsigned int)__cvta_generic_to_shared(sA);
    unsigned int sWh_u = (unsigned int)__cvta_generic_to_shared(sWh);
    unsigned int sWl_u = (unsigned int)__cvta_generic_to_shared(sWl);
    // A: matrix m -> rowadd=(m&1)*8, seg=(m>>1)*4
    int segA = (mq >> 1) * 4;
    unsigned int aBase[4];
    #pragma unroll
    for (int mf = 0; mf < 4; mf++) {
        int rowA = wm * 64 + mf * 16 + (mq & 1) * 8 + rq;
        aBase[mf] = sA_u + (unsigned int)(rowA * 64) * 4u;
    }
    // B: matrix m -> nf_in_pair=(m>>1), seg=(m&1)*4
    int segB = (mq & 1) * 4;
    unsigned int bOffN[2];
    #pragma unroll
    for (int pr = 0; pr < 2; pr++) {
        int n = wn * 32 + (pr * 2 + (mq >> 1)) * 8 + rq;
        bOffN[pr] = (unsigned int)(n * 64) * 4u;
    }

    for (int tile = blockIdx.x; tile < NTILES_MMA; tile += gridDim.x) {
        int rbase = tile * 128;
        float acc[4][4][4];
        #pragma unroll
        for (int mf = 0; mf < 4; mf++)
            #pragma unroll
            for (int nf = 0; nf < 4; nf++)
                #pragma unroll
                for (int q = 0; q < 4; q++) acc[mf][nf][q] = 0.f;

        #pragma unroll 1
        for (int kc = 0; kc < 2; kc++) {
            __syncthreads();
            const uint4* src = kc ? LXh : Ahin;
            for (int idx = tid; idx < 2048; idx += 256) {
                int r = idx >> 4, u4 = idx & 15;
                uint4 w = __ldg(src + (size_t)(rbase + r) * 16 + u4);
                int d = r * 64 + ((u4 * 4) ^ ((r & 7) << 2));
                *reinterpret_cast<uint4*>(sA + d) = w;
            }
            for (int idx = tid; idx < 2048; idx += 256) {
                int n = idx >> 4, q4 = idx & 15;
                int o0 = q4 * 4;
                int sw = (n & 7) << 2;
                int d = n * 64 + (o0 ^ sw);
                uint4 wh = __ldg(reinterpret_cast<const uint4*>(Wh32 + n * 128 + kc * 64 + o0));
                uint4 wl = __ldg(reinterpret_cast<const uint4*>(Wl32 + n * 128 + kc * 64 + o0));
                *reinterpret_cast<uint4*>(sWh + d) = wh;
                *reinterpret_cast<uint4*>(sWl + d) = wl;
            }
            __syncthreads();
            #pragma unroll 1
            for (int s = 0; s < 8; s++) {
                unsigned int colA = (unsigned int)(((s * 8 + segA) ^ swq) * 4);
                unsigned int colB = (unsigned int)(((s * 8 + segB) ^ swq) * 4);
                unsigned int af[4][4];
                #pragma unroll
                for (int mf = 0; mf < 4; mf++)
                    ldsm_x4(af[mf], aBase[mf] + colA);
                unsigned int bh[2][4], bl[2][4];
                ldsm_x4(bh[0], sWh_u + bOffN[0] + colB);
                ldsm_x4(bh[1], sWh_u + bOffN[1] + colB);
                #pragma unroll
                for (int pr = 0; pr < 2; pr++)
                    #pragma unroll
                    for (int nfi = 0; nfi < 2; nfi++) {
                        int nf = pr * 2 + nfi;
                        #pragma unroll
                        for (int mf = 0; mf < 4; mf++)
                            mma_f16(acc[mf][nf], af[mf], bh[pr][nfi * 2], bh[pr][nfi * 2 + 1]);
                    }
                ldsm_x4(bl[0], sWl_u + bOffN[0] + colB);
                ldsm_x4(bl[1], sWl_u + bOffN[1] + colB);
                #pragma unroll
                for (int pr = 0; pr < 2; pr++)
                    #pragma unroll
                    for (int nfi = 0; nfi < 2; nfi++) {
                        int nf = pr * 2 + nfi;
                        #pragma unroll
                        for (int mf = 0; mf < 4; mf++)
                            mma_f16(acc[mf][nf], af[mf], bl[pr][nfi * 2], bl[pr][nfi * 2 + 1]);
                    }
            }
        }
        // epilogue
        #pragma unroll
        for (int mf = 0; mf < 4; mf++) {
            int row0 = rbase + wm * 64 + mf * 16 + g;
            int row1 = row0 + 8;
            #pragma unroll
            for (int nf = 0; nf < 4; nf++) {
                int c0 = wn * 32 + nf * 8 + t2 * 2;
                float b0 = sBias[c0], b1 = sBias[c0 + 1];
                float x00 = acc[mf][nf][0] + b0, x01 = acc[mf][nf][1] + b1;
                float x10 = acc[mf][nf][2] + b0, x11 = acc[mf][nf][3] + b1;
                if (row0 < ROWS_TOT) {
                    if (has_res) {
                        float2 rv = *reinterpret_cast<const float2*>(res + (size_t)row0 * CC + c0);
                        x00 += rv.x; x01 += rv.y;
                    }
                    if (store_x) *reinterpret_cast<float2*>(xout + (size_t)row0 * CC + c0) = make_float2(x00, x01);
                    float e00 = eluf(x00), e01 = eluf(x01);
                    if (store_a) *reinterpret_cast<float2*>(Aout + (size_t)row0 * CC + c0) = make_float2(e00, e01);
                    Ahout[(size_t)row0 * 64 + (c0 >> 1)] = __floats2half2_rn(e00, e01);
                    stS[nf][0] += e00; stS[nf][1] += e01;
                    stQ[nf][0] += e00 * e00; stQ[nf][1] += e01 * e01;
                }
                if (row1 < ROWS_TOT) {
                    if (has_res) {
                        float2 rv = *reinterpret_cast<const float2*>(res + (size_t)row1 * CC + c0);
                        x10 += rv.x; x11 += rv.y;
                    }
                    if (store_x) *reinterpret_cast<float2*>(xout + (size_t)row1 * CC + c0) = make_float2(x10, x11);
                    float e10 = eluf(x10), e11 = eluf(x11);
                    if (store_a) *reinterpret_cast<float2*>(Aout + (size_t)row1 * CC + c0) = make_float2(e10, e11);
                    Ahout[(size_t)row1 * 64 + (c0 >> 1)] = __floats2half2_rn(e10, e11);
                    stS[nf][0] += e10; stS[nf][1] += e11;
                    stQ[nf][0] += e10 * e10; stQ[nf][1] += e11 * e11;
                }
            }
        }
    }
    #pragma unroll
    for (int nf = 0; nf < 4; nf++) {
        #pragma unroll
        for (int c = 0; c < 2; c++) {
            float s = stS[nf][c], q = stQ[nf][c];
            #pragma unroll
            for (int off = 4; off < 32; off <<= 1) {
                s += __shfl_xor_sync(0xFFFFFFFFu, s, off);
                q += __shfl_xor_sync(0xFFFFFFFFu, q, off);
            }
            if (g == 0) {
                int ch = wn * 32 + nf * 8 + t2 * 2 + c;
                atomicAdd(&stats[ch], s);
                atomicAdd(&stats[128 + ch], q);
            }
        }
    }
}

__global__ __launch_bounds__(128) void k_final(
    const float* __restrict__ Ain, const float* __restrict__ Wf2,
    const float* __restrict__ bfp2, const float* __restrict__ Wmu,
    const float* __restrict__ bmu, const float* __restrict__ logvar,
    const float* __restrict__ inputs, float* __restrict__ out)
{
    extern __shared__ float sh[];
    float* sW = sh;
    float* sU = sh + 16384;
    __shared__ float sWmu[128 * 3];
    __shared__ float sred[4][8][3];
    int tid = threadIdx.x, warp = tid >> 5, lane = tid & 31;
    for (int idx = tid; idx < 16384; idx += 128) sW[idx] = Wf2[idx];
    for (int idx = tid; idx < 384; idx += 128) sWmu[idx] = Wmu[idx];
    float bias = bfp2[tid] + bfp2[128 + tid] + bfp2[256 + tid] + bfp2[384 + tid];
    float lv = logvar[0];
    for (int base = blockIdx.x * 8; base < ROWS_TOT; base += gridDim.x * 8) {
        __syncthreads();
        for (int idx = tid; idx < 1024; idx += 128) {
            int r = idx >> 7, k = idx & 127;
            sU[idx] = Ain[(size_t)(base + r) * CC + k];
        }
        __syncthreads();
        float acc[8];
        #pragma unroll
        for (int r = 0; r < 8; r++) acc[r] = bias;
        #pragma unroll 4
        for (int k = 0; k < 128; k++) {
            float w = sW[k * 128 + tid];
            #pragma unroll
            for (int r = 0; r < 8; r++) acc[r] += sU[r * 128 + k] * w;
        }
        float w0 = sWmu[tid * 3 + 0], w1 = sWmu[tid * 3 + 1], w2 = sWmu[tid * 3 + 2];
        #pragma unroll
        for (int r = 0; r < 8; r++) {
            float z = eluf(acc[r]);
            float p0 = z * w0, p1 = z * w1, p2 = z * w2;
            #pragma unroll
            for (int off = 16; off; off >>= 1) {
                p0 += __shfl_down_sync(0xFFFFFFFFu, p0, off);
                p1 += __shfl_down_sync(0xFFFFFFFFu, p1, off);
                p2 += __shfl_down_sync(0xFFFFFFFFu, p2, off);
            }
            if (lane == 0) { sred[warp][r][0] = p0; sred[warp][r][1] = p1; sred[warp][r][2] = p2; }
        }
        __syncthreads();
        if (tid < 24) {
            int r = tid / 3, j = tid - r * 3;
            float m = sred[0][r][j] + sred[1][r][j] + sred[2][r][j] + sred[3][r][j] + bmu[j];
            size_t row = base + r;
            out[row * 3 + j] = m + inputs[row * 3 + j];
            out[(size_t)ROWS_TOT * 3 + row * 3 + j] = lv;
        }
    }
}

extern "C" void kernel_launch(void* const* d_in, const int* in_sizes, int n_in,
                              void* d_out, int out_size)
{
    const float* inputs  = (const float*)d_in[0];
    const float* noise   = (const float*)d_in[1];
    const int*   L_rows  = (const int*)d_in[3];
    const int*   L_cols  = (const int*)d_in[4];
    const float* L_vals  = (const float*)d_in[5];
    const float* W_in    = (const float*)d_in[6];
    const float* b_in    = (const float*)d_in[7];
    const float* W_noise = (const float*)d_in[8];
    const float* b_noise = (const float*)d_in[9];
    const float* rn_gamma= (const float*)d_in[10];
    const float* rn_beta = (const float*)d_in[11];
    const float* rn_W    = (const float*)d_in[12];
    const float* rn_b    = (const float*)d_in[13];
    const float* bn2_g   = (const float*)d_in[14];
    const float* bn2_b   = (const float*)d_in[15];
    const float* W2      = (const float*)d_in[16];
    const float* b2      = (const float*)d_in[17];
    const float* W_mu    = (const float*)d_in[18];
    const float* b_mu    = (const float*)d_in[19];
    const float* logvar  = (const float*)d_in[20];
    float* out = (float*)d_out;

    float *X, *A, *sa, *sl, *bf, *Wf2, *bf2;
    unsigned int *Wh32, *Wl32;
    uint4 *Ah, *LXh;
    int2* csr;
    int *rowptr, *cnt, *cursor;
    cudaGetSymbolAddress((void**)&X, g_X);
    cudaGetSymbolAddress((void**)&A, g_A);
    cudaGetSymbolAddress((void**)&Ah, g_Ah);
    cudaGetSymbolAddress((void**)&LXh, g_LXh);
    cudaGetSymbolAddress((void**)&sa, g_stats_a);
    cudaGetSymbolAddress((void**)&sl, g_stats_l);
    cudaGetSymbolAddress((void**)&Wh32, g_Wh32);
    cudaGetSymbolAddress((void**)&Wl32, g_Wl32);
    cudaGetSymbolAddress((void**)&bf, g_bf);
    cudaGetSymbolAddress((void**)&Wf2, g_Wf2);
    cudaGetSymbolAddress((void**)&bf2, g_bf2);
    cudaGetSymbolAddress((void**)&csr, g_csr);
    cudaGetSymbolAddress((void**)&rowptr, g_rowptr);
    cudaGetSymbolAddress((void**)&cnt, g_cnt);
    cudaGetSymbolAddress((void**)&cursor, g_cursor);

    const int SMEM_GEMM = 24576 * 4 + 512;   // 98,816 B -> 2 CTAs/SM
    cudaFuncSetAttribute(k_gemm_mma, cudaFuncAttributeMaxDynamicSharedMemorySize, 100 * 1024);
    cudaFuncSetAttribute(k_final, cudaFuncAttributeMaxDynamicSharedMemorySize, 72 * 1024);

    k_inproj_hist<<<IP_BLOCKS + HIST_BLOCKS, 256>>>(
        inputs, noise, W_in, b_in, W_noise, b_noise,
        X, (__half*)Ah, sa, L_rows, cnt);
    k_scan<<<4, 1024>>>(cnt, rowptr, cursor);
    k_scatter<<<4096, 256>>>(L_rows, L_cols, L_vals, cursor, csr, cnt);

    for (int s = 0; s < 10; s++) {
        k_spmm<<<4096, 256>>>(Ah, rowptr, csr, LXh, sl + s * 256);
        k_fold<<<8, 128>>>(sa + s * 256, sl + s * 256,
                           rn_gamma + s * 256, rn_beta + s * 256,
                           rn_W + (size_t)s * 256 * 128, rn_b + s * 128,
                           Wh32, Wl32, (float*)0, bf);
        int odd = s & 1;
        k_gemm_mma<<<296, 256, SMEM_GEMM>>>(
            Ah, LXh, Wh32, Wl32, bf,
            X, odd, X, odd, A, (s == 9),
            (__half2*)Ah, sa + (s + 1) * 256);
    }

    k_fold<<<4, 128>>>(sa + 10 * 256, sa + 10 * 256, bn2_g, bn2_b, W2, b2,
                       (unsigned int*)0, (unsigned int*)0, Wf2, bf2);
    k_final<<<1024, 128, (16384 + 1024) * sizeof(float)>>>(
        A, Wf2, bf2, W_mu, b_mu, logvar, inputs, out);
}

// round 15
// speedup vs baseline: 1.1486x; 1.1486x over previous
#include <cuda_runtime.h>
#include <cuda_fp16.h>
#include <math.h>

#define BB 4
#define NN 50000
#define EE 800000
#define CC 128
#define ROWS_TOT 200000
#define ROWS_PAD 200064            // 1563 * 128
#define NTILES_MMA 1563
#define MINV (1.0f/200000.0f)

__device__ float g_X  [(size_t)ROWS_TOT * CC];
__device__ float g_A  [(size_t)ROWS_TOT * CC];
__device__ uint4 g_Ah [(size_t)ROWS_PAD * 16];          // pads stay zero (module init)
__device__ uint4 g_LXh[(size_t)ROWS_PAD * 16];          // pads stay zero (module init)
__device__ int2  g_csr[(size_t)BB * EE];
__device__ int   g_rowptr[BB * (NN + 1)];
__device__ int   g_cnt[ROWS_TOT];                       // zero at load; re-zeroed by k_scatter
__device__ int   g_cursor[ROWS_TOT];
__device__ float g_stats_a[11 * 256];                   // zero at load; re-zeroed by k_fold
__device__ float g_stats_l[10 * 256];
__device__ unsigned int g_Wh32[128 * 128];
__device__ unsigned int g_Wl32[128 * 128];
__device__ float g_bf[8 * 128];
__device__ float g_Wf2[128 * 128];
__device__ float g_bf2[4 * 128];

__device__ __forceinline__ float eluf(float v) { return v > 0.f ? v : expm1f(v); }
__device__ __forceinline__ float4 fma4(float4 w, float s, float4 a) {
    a.x += w.x * s; a.y += w.y * s; a.z += w.z * s; a.w += w.w * s; return a;
}
__device__ __forceinline__ float4 h4_to_f4(uint2 w) {
    __half2 a = *reinterpret_cast<__half2*>(&w.x);
    __half2 b = *reinterpret_cast<__half2*>(&w.y);
    float2 fa = __half22float2(a), fb = __half22float2(b);
    return make_float4(fa.x, fa.y, fb.x, fb.y);
}
__device__ __forceinline__ uint2 f4_to_h4(float4 v) {
    __half2 a = __floats2half2_rn(v.x, v.y);
    __half2 b = __floats2half2_rn(v.z, v.w);
    uint2 u;
    u.x = *reinterpret_cast<unsigned*>(&a);
    u.y = *reinterpret_cast<unsigned*>(&b);
    return u;
}
__device__ __forceinline__ void mma_f16(float* d, const unsigned int* a,
                                        unsigned int b0, unsigned int b1) {
    asm volatile(
        "mma.sync.aligned.m16n8k16.row.col.f32.f16.f16.f32 "
        "{%0,%1,%2,%3}, {%4,%5,%6,%7}, {%8,%9}, {%0,%1,%2,%3};"
        : "+f"(d[0]), "+f"(d[1]), "+f"(d[2]), "+f"(d[3])
        : "r"(a[0]), "r"(a[1]), "r"(a[2]), "r"(a[3]), "r"(b0), "r"(b1));
}
__device__ __forceinline__ void ldsm_x4(unsigned int* r, unsigned int addr) {
    asm volatile("ldmatrix.sync.aligned.m8n8.x4.shared.b16 {%0,%1,%2,%3}, [%4];"
        : "=r"(r[0]), "=r"(r[1]), "=r"(r[2]), "=r"(r[3]) : "r"(addr));
}

// ---------------- fused input projection + edge histogram ----------------
#define IP_BLOCKS 1024
#define HIST_BLOCKS 2048
__global__ __launch_bounds__(256) void k_inproj_hist(
    const float* __restrict__ inputs, const float* __restrict__ noise,
    const float* __restrict__ Win, const float* __restrict__ bin,
    const float* __restrict__ Wn, const float* __restrict__ bn,
    float* __restrict__ X, __half* __restrict__ Ah, float* __restrict__ stats,
    const int* __restrict__ L_rows, int* __restrict__ cnt)
{
    int tid = threadIdx.x;
    if (blockIdx.x >= IP_BLOCKS) {
        int stride = HIST_BLOCKS * 256;
        for (int t = (blockIdx.x - IP_BLOCKS) * 256 + tid; t < BB * EE; t += stride) {
            int b = t / EE;
            atomicAdd(&cnt[b * NN + L_rows[t]], 1);
        }
        return;
    }
    __shared__ float sU[8][104];
    int half = tid >> 7;
    int t128 = tid & 127;
    float bias = bin[t128] + bn[t128];
    float psum = 0.f, psq = 0.f;
    for (int base = blockIdx.x * 8; base < ROWS_TOT; base += IP_BLOCKS * 8) {
        __syncthreads();
        for (int idx = tid; idx < 8 * 103; idx += 256) {
            int r = idx / 103, k = idx - r * 103;
            int row = base + r;
            sU[r][k] = (k < 100) ? noise[(size_t)row * 100 + k]
                                 : inputs[(size_t)row * 3 + (k - 100)];
        }
        __syncthreads();
        int r0 = half * 4;
        float acc0 = bias, acc1 = bias, acc2 = bias, acc3 = bias;
        #pragma unroll 5
        for (int kq = 0; kq < 25; kq++) {
            int k = kq * 4;
            float w0 = __ldg(&Wn[(k + 0) * 128 + t128]);
            float w1 = __ldg(&Wn[(k + 1) * 128 + t128]);
            float w2 = __ldg(&Wn[(k + 2) * 128 + t128]);
            float w3 = __ldg(&Wn[(k + 3) * 128 + t128]);
            float4 u0 = *reinterpret_cast<const float4*>(&sU[r0 + 0][k]);
            float4 u1 = *reinterpret_cast<const float4*>(&sU[r0 + 1][k]);
            float4 u2 = *reinterpret_cast<const float4*>(&sU[r0 + 2][k]);
            float4 u3 = *reinterpret_cast<const float4*>(&sU[r0 + 3][k]);
            acc0 += u0.x * w0 + u0.y * w1 + u0.z * w2 + u0.w * w3;
            acc1 += u1.x * w0 + u1.y * w1 + u1.z * w2 + u1.w * w3;
            acc2 += u2.x * w0 + u2.y * w1 + u2.z * w2 + u2.w * w3;
            acc3 += u3.x * w0 + u3.y * w1 + u3.z * w2 + u3.w * w3;
        }
        #pragma unroll
        for (int k = 0; k < 3; k++) {
            float w = __ldg(&Win[k * 128 + t128]);
            acc0 += sU[r0 + 0][100 + k] * w;
            acc1 += sU[r0 + 1][100 + k] * w;
            acc2 += sU[r0 + 2][100 + k] * w;
            acc3 += sU[r0 + 3][100 + k] * w;
        }
        float accs[4] = {acc0, acc1, acc2, acc3};
        #pragma unroll
        for (int r = 0; r < 4; r++) {
            int row = base + r0 + r;
            float v = accs[r];
            X[(size_t)row * CC + t128] = v;
            float e = eluf(v);
            Ah[(size_t)row * CC + t128] = __float2half_rn(e);
            psum += e; psq += e * e;
        }
    }
    atomicAdd(&stats[t128], psum);
    atomicAdd(&stats[128 + t128], psq);
}

__global__ void k_scan(const int* __restrict__ cnt, int* rowptr, int* cursor) {
    __shared__ int sh[1024];
    int b = blockIdx.x, tid = threadIdx.x;
    const int CH = 49;
    int start = tid * CH;
    int end = min(start + CH, NN);
    int s = 0;
    for (int i = start; i < end; i++) s += cnt[b * NN + i];
    sh[tid] = s;
    __syncthreads();
    for (int off = 1; off < 1024; off <<= 1) {
        int t = (tid >= off) ? sh[tid - off] : 0;
        __syncthreads();
        sh[tid] += t;
        __syncthreads();
    }
    int run = (tid == 0) ? 0 : sh[tid - 1];
    for (int i = start; i < end; i++) {
        rowptr[b * (NN + 1) + i] = run;
        cursor[b * NN + i] = run;
        run += cnt[b * NN + i];
    }
    if (tid == 1023) rowptr[b * (NN + 1) + NN] = run;
}

__global__ void k_scatter(const int* __restrict__ L_rows, const int* __restrict__ L_cols,
                          const float* __restrict__ L_vals, int* cursor, int2* csr,
                          int* cnt) {
    int stride = gridDim.x * blockDim.x;
    int t0 = blockIdx.x * blockDim.x + threadIdx.x;
    for (int i = t0; i < ROWS_TOT; i += stride) cnt[i] = 0;
    for (int t = t0; t < BB * EE; t += stride) {
        int b = t / EE;
        int r = L_rows[t];
        int pos = atomicAdd(&cursor[b * NN + r], 1);
        int2 e; e.x = L_cols[t]; e.y = __float_as_int(L_vals[t]);
        csr[(size_t)b * EE + pos] = e;
    }
}

// ---------------- CSR SpMM (R13 measured-best): 1 row/warp, uint2 fp16 gather, MLP=4 ----------------
__global__ __launch_bounds__(256) void k_spmm(
    const uint2* __restrict__ Ah2, const int* __restrict__ rowptr,
    const int2* __restrict__ csr, uint2* __restrict__ LXh2, float* __restrict__ stats)
{
    __shared__ float s_sum[128], s_sq[128];
    int tid = threadIdx.x;
    if (tid < 128) { s_sum[tid] = 0.f; s_sq[tid] = 0.f; }
    __syncthreads();
    int warp = tid >> 5, lane = tid & 31;
    float4 psum = {0,0,0,0}, psq = {0,0,0,0};
    for (int g = blockIdx.x * 8 + warp; g < ROWS_TOT; g += gridDim.x * 8) {
        int b = g / NN;
        int i = g - b * NN;
        int p0 = rowptr[b * (NN + 1) + i];
        int p1 = rowptr[b * (NN + 1) + i + 1];
        const int2* ev = csr + (size_t)b * EE;
        const uint2* Ab = Ah2 + (size_t)b * NN * 32;
        float4 a0 = {0,0,0,0}, a1 = {0,0,0,0}, a2 = {0,0,0,0}, a3 = {0,0,0,0};
        int p = p0;
        for (; p + 4 <= p1; p += 4) {
            int2 e0 = __ldg(&ev[p + 0]);
            int2 e1 = __ldg(&ev[p + 1]);
            int2 e2 = __ldg(&ev[p + 2]);
            int2 e3 = __ldg(&ev[p + 3]);
            uint2 w0 = __ldg(Ab + (size_t)e0.x * 32 + lane);
            uint2 w1 = __ldg(Ab + (size_t)e1.x * 32 + lane);
            uint2 w2 = __ldg(Ab + (size_t)e2.x * 32 + lane);
            uint2 w3 = __ldg(Ab + (size_t)e3.x * 32 + lane);
            a0 = fma4(h4_to_f4(w0), __int_as_float(e0.y), a0);
            a1 = fma4(h4_to_f4(w1), __int_as_float(e1.y), a1);
            a2 = fma4(h4_to_f4(w2), __int_as_float(e2.y), a2);
            a3 = fma4(h4_to_f4(w3), __int_as_float(e3.y), a3);
        }
        for (; p < p1; p++) {
            int2 e = __ldg(&ev[p]);
            a0 = fma4(h4_to_f4(__ldg(Ab + (size_t)e.x * 32 + lane)), __int_as_float(e.y), a0);
        }
        float4 acc;
        acc.x = (a0.x + a1.x) + (a2.x + a3.x);
        acc.y = (a0.y + a1.y) + (a2.y + a3.y);
        acc.z = (a0.z + a1.z) + (a2.z + a3.z);
        acc.w = (a0.w + a1.w) + (a2.w + a3.w);
        LXh2[(size_t)g * 32 + lane] = f4_to_h4(acc);
        psum.x += acc.x; psum.y += acc.y; psum.z += acc.z; psum.w += acc.w;
        psq.x += acc.x*acc.x; psq.y += acc.y*acc.y; psq.z += acc.z*acc.z; psq.w += acc.w*acc.w;
    }
    int ch = lane * 4;
    atomicAdd(&s_sum[ch+0], psum.x); atomicAdd(&s_sum[ch+1], psum.y);
    atomicAdd(&s_sum[ch+2], psum.z); atomicAdd(&s_sum[ch+3], psum.w);
    atomicAdd(&s_sq[ch+0], psq.x); atomicAdd(&s_sq[ch+1], psq.y);
    atomicAdd(&s_sq[ch+2], psq.z); atomicAdd(&s_sq[ch+3], psq.w);
    __syncthreads();
    if (tid < 128) {
        atomicAdd(&stats[tid], s_sum[tid]);
        atomicAdd(&stats[128 + tid], s_sq[tid]);
    }
}

__global__ __launch_bounds__(128) void k_fold(
    float* __restrict__ sa, float* __restrict__ sl,
    const float* __restrict__ gamma, const float* __restrict__ beta,
    const float* __restrict__ W, const float* __restrict__ b,
    unsigned int* __restrict__ Wh32, unsigned int* __restrict__ Wl32,
    float* __restrict__ Wf2, float* bfp)
{
    __shared__ float s_scale[32], s_shift[32];
    int bi = blockIdx.x;
    int tid = threadIdx.x;
    if (tid < 32) {
        int c = bi * 32 + tid;
        float sum, sq;
        if (c < 128) { sum = sa[c]; sq = sa[128 + c]; }
        else         { sum = sl[c - 128]; sq = sl[c]; }
        float m = sum * MINV;
        float var = sq * MINV - m * m;
        float r = rsqrtf(var + 1e-5f);
        float sc = gamma[c] * r;
        s_scale[tid] = sc;
        s_shift[tid] = beta[c] - m * sc;
        if (c < 128) { sa[c] = 0.f; sa[128 + c] = 0.f; }
        else         { sl[c - 128] = 0.f; sl[c] = 0.f; }
    }
    __syncthreads();
    float bias = (bi == 0) ? b[tid] : 0.f;
    #pragma unroll 4
    for (int j = 0; j < 32; j += 2) {
        int c0 = bi * 32 + j;
        float w0r = W[c0 * 128 + tid];
        float w1r = W[(c0 + 1) * 128 + tid];
        float w0 = w0r * s_scale[j];
        float w1 = w1r * s_scale[j + 1];
        bias += s_shift[j] * w0r + s_shift[j + 1] * w1r;
        if (Wh32) {
            __half h0 = __float2half_rn(w0);
            __half h1 = __float2half_rn(w1);
            float l0 = w0 - __half2float(h0);
            float l1 = w1 - __half2float(h1);
            __half2 hw = __halves2half2(h0, h1);
            __half2 lw = __floats2half2_rn(l0, l1);
            Wh32[tid * 128 + (c0 >> 1)] = *reinterpret_cast<unsigned int*>(&hw);
            Wl32[tid * 128 + (c0 >> 1)] = *reinterpret_cast<unsigned int*>(&lw);
        } else {
            Wf2[c0 * 128 + tid] = w0;
            Wf2[(c0 + 1) * 128 + tid] = w1;
        }
    }
    bfp[bi * 128 + tid] = bias;
}

// ---------------- main GEMM: fp16 MMA, ldmatrix fragment loads, 2 CTAs/SM ----------------
__global__ __launch_bounds__(256, 2) void k_gemm_mma(
    const uint4* __restrict__ Ahin, const uint4* __restrict__ LXh,
    const unsigned int* __restrict__ Wh32, const unsigned int* __restrict__ Wl32,
    const float* __restrict__ bfp, const float* __restrict__ res, int has_res,
    float* __restrict__ xout, int store_x,
    float* __restrict__ Aout, int store_a,
    __half2* __restrict__ Ahout, float* __restrict__ stats)
{
    extern __shared__ unsigned int sm[];
    unsigned int* sWh = sm;              // 8192 words: [n][o^sw], current kc half
    unsigned int* sWl = sm + 8192;
    unsigned int* sA  = sm + 16384;      // 8192: 128 rows x 64 kpairs
    float* sBias = (float*)(sm + 24576);

    int tid = threadIdx.x, warp = tid >> 5, lane = tid & 31;
    int wm = warp >> 2, wn = warp & 3;
    int g = lane >> 2, t2 = lane & 3;

    if (tid < 128) {
        float bsum = 0.f;
        #pragma unroll
        for (int j = 0; j < 8; j++) bsum += bfp[j * 128 + tid];
        sBias[tid] = bsum;
    }
    float stS[4][2], stQ[4][2];
    #pragma unroll
    for (int i = 0; i < 4; i++) { stS[i][0]=0.f; stS[i][1]=0.f; stQ[i][0]=0.f; stQ[i][1]=0.f; }

    // ldmatrix lane decomposition
    int mq = lane >> 3, rq = lane & 7;
    int swq = rq << 2;
    unsigned int sA_u  = (unsigned int)__cvta_generic_to_shared(sA);
    unsigned int sWh_u = (unsigned int)__cvta_generic_to_shared(sWh);
    unsigned int sWl_u = (unsigned int)__cvta_generic_to_shared(sWl);
    int segA = (mq >> 1) * 4;
    unsigned int aBase[4];
    #pragma unroll
    for (int mf = 0; mf < 4; mf++) {
        int rowA = wm * 64 + mf * 16 + (mq & 1) * 8 + rq;
        aBase[mf] = sA_u + (unsigned int)(rowA * 64) * 4u;
    }
    int segB = (mq & 1) * 4;
    unsigned int bOffN[2];
    #pragma unroll
    for (int pr = 0; pr < 2; pr++) {
        int n = wn * 32 + (pr * 2 + (mq >> 1)) * 8 + rq;
        bOffN[pr] = (unsigned int)(n * 64) * 4u;
    }

    for (int tile = blockIdx.x; tile < NTILES_MMA; tile += gridDim.x) {
        int rbase = tile * 128;
        float acc[4][4][4];
        #pragma unroll
        for (int mf = 0; mf < 4; mf++)
            #pragma unroll
            for (int nf = 0; nf < 4; nf++)
                #pragma unroll
                for (int q = 0; q < 4; q++) acc[mf][nf][q] = 0.f;

        #pragma unroll 1
        for (int kc = 0; kc < 2; kc++) {
            __syncthreads();
            const uint4* src = kc ? LXh : Ahin;
            for (int idx = tid; idx < 2048; idx += 256) {
                int r = idx >> 4, u4 = idx & 15;
                uint4 w = __ldg(src + (size_t)(rbase + r) * 16 + u4);
                int d = r * 64 + ((u4 * 4) ^ ((r & 7) << 2));
                *reinterpret_cast<uint4*>(sA + d) = w;
            }
            for (int idx = tid; idx < 2048; idx += 256) {
                int n = idx >> 4, q4 = idx & 15;
                int o0 = q4 * 4;
                int sw = (n & 7) << 2;
                int d = n * 64 + (o0 ^ sw);
                uint4 wh = __ldg(reinterpret_cast<const uint4*>(Wh32 + n * 128 + kc * 64 + o0));
                uint4 wl = __ldg(reinterpret_cast<const uint4*>(Wl32 + n * 128 + kc * 64 + o0));
                *reinterpret_cast<uint4*>(sWh + d) = wh;
                *reinterpret_cast<uint4*>(sWl + d) = wl;
            }
            __syncthreads();
            #pragma unroll 1
            for (int s = 0; s < 8; s++) {
                unsigned int colA = (unsigned int)(((s * 8 + segA) ^ swq) * 4);
                unsigned int colB = (unsigned int)(((s * 8 + segB) ^ swq) * 4);
                unsigned int af[4][4];
                #pragma unroll
                for (int mf = 0; mf < 4; mf++)
                    ldsm_x4(af[mf], aBase[mf] + colA);
                unsigned int bh[2][4], bl[2][4];
                ldsm_x4(bh[0], sWh_u + bOffN[0] + colB);
                ldsm_x4(bh[1], sWh_u + bOffN[1] + colB);
                #pragma unroll
                for (int pr = 0; pr < 2; pr++)
                    #pragma unroll
                    for (int nfi = 0; nfi < 2; nfi++) {
                        int nf = pr * 2 + nfi;
                        #pragma unroll
                        for (int mf = 0; mf < 4; mf++)
                            mma_f16(acc[mf][nf], af[mf], bh[pr][nfi * 2], bh[pr][nfi * 2 + 1]);
                    }
                ldsm_x4(bl[0], sWl_u + bOffN[0] + colB);
                ldsm_x4(bl[1], sWl_u + bOffN[1] + colB);
                #pragma unroll
                for (int pr = 0; pr < 2; pr++)
                    #pragma unroll
                    for (int nfi = 0; nfi < 2; nfi++) {
                        int nf = pr * 2 + nfi;
                        #pragma unroll
                        for (int mf = 0; mf < 4; mf++)
                            mma_f16(acc[mf][nf], af[mf], bl[pr][nfi * 2], bl[pr][nfi * 2 + 1]);
                    }
            }
        }
        // epilogue
        #pragma unroll
        for (int mf = 0; mf < 4; mf++) {
            int row0 = rbase + wm * 64 + mf * 16 + g;
            int row1 = row0 + 8;
            #pragma unroll
            for (int nf = 0; nf < 4; nf++) {
                int c0 = wn * 32 + nf * 8 + t2 * 2;
                float b0 = sBias[c0], b1 = sBias[c0 + 1];
                float x00 = acc[mf][nf][0] + b0, x01 = acc[mf][nf][1] + b1;
                float x10 = acc[mf][nf][2] + b0, x11 = acc[mf][nf][3] + b1;
                if (row0 < ROWS_TOT) {
                    if (has_res) {
                        float2 rv = *reinterpret_cast<const float2*>(res + (size_t)row0 * CC + c0);
                        x00 += rv.x; x01 += rv.y;
                    }
                    if (store_x) *reinterpret_cast<float2*>(xout + (size_t)row0 * CC + c0) = make_float2(x00, x01);
                    float e00 = eluf(x00), e01 = eluf(x01);
                    if (store_a) *reinterpret_cast<float2*>(Aout + (size_t)row0 * CC + c0) = make_float2(e00, e01);
                    Ahout[(size_t)row0 * 64 + (c0 >> 1)] = __floats2half2_rn(e00, e01);
                    stS[nf][0] += e00; stS[nf][1] += e01;
                    stQ[nf][0] += e00 * e00; stQ[nf][1] += e01 * e01;
                }
                if (row1 < ROWS_TOT) {
                    if (has_res) {
                        float2 rv = *reinterpret_cast<const float2*>(res + (size_t)row1 * CC + c0);
                        x10 += rv.x; x11 += rv.y;
                    }
                    if (store_x) *reinterpret_cast<float2*>(xout + (size_t)row1 * CC + c0) = make_float2(x10, x11);
                    float e10 = eluf(x10), e11 = eluf(x11);
                    if (store_a) *reinterpret_cast<float2*>(Aout + (size_t)row1 * CC + c0) = make_float2(e10, e11);
                    Ahout[(size_t)row1 * 64 + (c0 >> 1)] = __floats2half2_rn(e10, e11);
                    stS[nf][0] += e10; stS[nf][1] += e11;
                    stQ[nf][0] += e10 * e10; stQ[nf][1] += e11 * e11;
                }
            }
        }
    }
    #pragma unroll
    for (int nf = 0; nf < 4; nf++) {
        #pragma unroll
        for (int c = 0; c < 2; c++) {
            float s = stS[nf][c], q = stQ[nf][c];
            #pragma unroll
            for (int off = 4; off < 32; off <<= 1) {
                s += __shfl_xor_sync(0xFFFFFFFFu, s, off);
                q += __shfl_xor_sync(0xFFFFFFFFu, q, off);
            }
            if (g == 0) {
                int ch = wn * 32 + nf * 8 + t2 * 2 + c;
                atomicAdd(&stats[ch], s);
                atomicAdd(&stats[128 + ch], q);
            }
        }
    }
}

__global__ __launch_bounds__(128) void k_final(
    const float* __restrict__ Ain, const float* __restrict__ Wf2,
    const float* __restrict__ bfp2, const float* __restrict__ Wmu,
    const float* __restrict__ bmu, const float* __restrict__ logvar,
    const float* __restrict__ inputs, float* __restrict__ out)
{
    extern __shared__ float sh[];
    float* sW = sh;
    float* sU = sh + 16384;
    __shared__ float sWmu[128 * 3];
    __shared__ float sred[4][8][3];
    int tid = threadIdx.x, warp = tid >> 5, lane = tid & 31;
    for (int idx = tid; idx < 16384; idx += 128) sW[idx] = Wf2[idx];
    for (int idx = tid; idx < 384; idx += 128) sWmu[idx] = Wmu[idx];
    float bias = bfp2[tid] + bfp2[128 + tid] + bfp2[256 + tid] + bfp2[384 + tid];
    float lv = logvar[0];
    for (int base = blockIdx.x * 8; base < ROWS_TOT; base += gridDim.x * 8) {
        __syncthreads();
        for (int idx = tid; idx < 1024; idx += 128) {
            int r = idx >> 7, k = idx & 127;
            sU[idx] = Ain[(size_t)(base + r) * CC + k];
        }
        __syncthreads();
        float acc[8];
        #pragma unroll
        for (int r = 0; r < 8; r++) acc[r] = bias;
        #pragma unroll 4
        for (int k = 0; k < 128; k++) {
            float w = sW[k * 128 + tid];
            #pragma unroll
            for (int r = 0; r < 8; r++) acc[r] += sU[r * 128 + k] * w;
        }
        float w0 = sWmu[tid * 3 + 0], w1 = sWmu[tid * 3 + 1], w2 = sWmu[tid * 3 + 2];
        #pragma unroll
        for (int r = 0; r < 8; r++) {
            float z = eluf(acc[r]);
            float p0 = z * w0, p1 = z * w1, p2 = z * w2;
            #pragma unroll
            for (int off = 16; off; off >>= 1) {
                p0 += __shfl_down_sync(0xFFFFFFFFu, p0, off);
                p1 += __shfl_down_sync(0xFFFFFFFFu, p1, off);
                p2 += __shfl_down_sync(0xFFFFFFFFu, p2, off);
            }
            if (lane == 0) { sred[warp][r][0] = p0; sred[warp][r][1] = p1; sred[warp][r][2] = p2; }
        }
        __syncthreads();
        if (tid < 24) {
            int r = tid / 3, j = tid - r * 3;
            float m = sred[0][r][j] + sred[1][r][j] + sred[2][r][j] + sred[3][r][j] + bmu[j];
            size_t row = base + r;
            out[row * 3 + j] = m + inputs[row * 3 + j];
            out[(size_t)ROWS_TOT * 3 + row * 3 + j] = lv;
        }
    }
}

extern "C" void kernel_launch(void* const* d_in, const int* in_sizes, int n_in,
                              void* d_out, int out_size)
{
    const float* inputs  = (const float*)d_in[0];
    const float* noise   = (const float*)d_in[1];
    const int*   L_rows  = (const int*)d_in[3];
    const int*   L_cols  = (const int*)d_in[4];
    const float* L_vals  = (const float*)d_in[5];
    const float* W_in    = (const float*)d_in[6];
    const float* b_in    = (const float*)d_in[7];
    const float* W_noise = (const float*)d_in[8];
    const float* b_noise = (const float*)d_in[9];
    const float* rn_gamma= (const float*)d_in[10];
    const float* rn_beta = (const float*)d_in[11];
    const float* rn_W    = (const float*)d_in[12];
    const float* rn_b    = (const float*)d_in[13];
    const float* bn2_g   = (const float*)d_in[14];
    const float* bn2_b   = (const float*)d_in[15];
    const float* W2      = (const float*)d_in[16];
    const float* b2      = (const float*)d_in[17];
    const float* W_mu    = (const float*)d_in[18];
    const float* b_mu    = (const float*)d_in[19];
    const float* logvar  = (const float*)d_in[20];
    float* out = (float*)d_out;

    float *X, *A, *sa, *sl, *bf, *Wf2, *bf2;
    unsigned int *Wh32, *Wl32;
    uint4 *Ah, *LXh;
    int2* csr;
    int *rowptr, *cnt, *cursor;
    cudaGetSymbolAddress((void**)&X, g_X);
    cudaGetSymbolAddress((void**)&A, g_A);
    cudaGetSymbolAddress((void**)&Ah, g_Ah);
    cudaGetSymbolAddress((void**)&LXh, g_LXh);
    cudaGetSymbolAddress((void**)&sa, g_stats_a);
    cudaGetSymbolAddress((void**)&sl, g_stats_l);
    cudaGetSymbolAddress((void**)&Wh32, g_Wh32);
    cudaGetSymbolAddress((void**)&Wl32, g_Wl32);
    cudaGetSymbolAddress((void**)&bf, g_bf);
    cudaGetSymbolAddress((void**)&Wf2, g_Wf2);
    cudaGetSymbolAddress((void**)&bf2, g_bf2);
    cudaGetSymbolAddress((void**)&csr, g_csr);
    cudaGetSymbolAddress((void**)&rowptr, g_rowptr);
    cudaGetSymbolAddress((void**)&cnt, g_cnt);
    cudaGetSymbolAddress((void**)&cursor, g_cursor);

    const int SMEM_GEMM = 24576 * 4 + 512;   // 98,816 B -> 2 CTAs/SM
    cudaFuncSetAttribute(k_gemm_mma, cudaFuncAttributeMaxDynamicSharedMemorySize, 100 * 1024);
    cudaFuncSetAttribute(k_final, cudaFuncAttributeMaxDynamicSharedMemorySize, 72 * 1024);

    k_inproj_hist<<<IP_BLOCKS + HIST_BLOCKS, 256>>>(
        inputs, noise, W_in, b_in, W_noise, b_noise,
        X, (__half*)Ah, sa, L_rows, cnt);
    k_scan<<<4, 1024>>>(cnt, rowptr, cursor);
    k_scatter<<<4096, 256>>>(L_rows, L_cols, L_vals, cursor, csr, cnt);

    for (int s = 0; s < 10; s++) {
        k_spmm<<<4096, 256>>>((const uint2*)Ah, rowptr, csr, (uint2*)LXh, sl + s * 256);
        k_fold<<<8, 128>>>(sa + s * 256, sl + s * 256,
                           rn_gamma + s * 256, rn_beta + s * 256,
                           rn_W + (size_t)s * 256 * 128, rn_b + s * 128,
                           Wh32, Wl32, (float*)0, bf);
        int odd = s & 1;
        k_gemm_mma<<<296, 256, SMEM_GEMM>>>(
            Ah, LXh, Wh32, Wl32, bf,
            X, odd, X, odd, A, (s == 9),
            (__half2*)Ah, sa + (s + 1) * 256);
    }

    k_fold<<<4, 128>>>(sa + 10 * 256, sa + 10 * 256, bn2_g, bn2_b, W2, b2,
                       (unsigned int*)0, (unsigned int*)0, Wf2, bf2);
    k_final<<<1024, 128, (16384 + 1024) * sizeof(float)>>>(
        A, Wf2, bf2, W_mu, b_mu, logvar, inputs, out);
}

// round 16
// speedup vs baseline: 1.3521x; 1.1772x over previous
#include <cuda_runtime.h>
#include <cuda_fp16.h>
#include <math.h>

#define BB 4
#define NN 50000
#define EE 800000
#define CC 128
#define ROWS_TOT 200000
#define ROWS_PAD 200064            // 1563 * 128
#define NTILES_MMA 1563
#define MINV (1.0f/200000.0f)

__device__ float g_X  [(size_t)ROWS_TOT * CC];
__device__ float g_A  [(size_t)ROWS_TOT * CC];
__device__ uint4 g_Ah [(size_t)ROWS_PAD * 16];          // pads stay zero (module init)
__device__ uint4 g_LXh[(size_t)ROWS_PAD * 16];          // pads stay zero (module init)
__device__ int2  g_csr[(size_t)BB * EE];
__device__ int   g_rowptr[BB * (NN + 1)];
__device__ int   g_cnt[ROWS_TOT];                       // zero at load; re-zeroed by k_scatter
__device__ int   g_cursor[ROWS_TOT];
__device__ float g_stats_a[11 * 256];                   // zero at load; re-zeroed by k_fold
__device__ float g_stats_l[10 * 256];
__device__ unsigned int g_Wh32[128 * 128];
__device__ unsigned int g_Wl32[128 * 128];
__device__ float g_bf[32 * 128];                        // 32 partial biases (8 ch/block)
__device__ float g_Wf2[128 * 128];
__device__ float g_bf2[16 * 128];                       // 16 partial biases

__device__ __forceinline__ float eluf(float v) { return v > 0.f ? v : expm1f(v); }
__device__ __forceinline__ float4 ld4(const float* p) { return *reinterpret_cast<const float4*>(p); }
__device__ __forceinline__ void st4(float* p, float4 v) { *reinterpret_cast<float4*>(p) = v; }
__device__ __forceinline__ float4 fma4(float4 w, float s, float4 a) {
    a.x += w.x * s; a.y += w.y * s; a.z += w.z * s; a.w += w.w * s; return a;
}
__device__ __forceinline__ float4 h4_to_f4(uint2 w) {
    __half2 a = *reinterpret_cast<__half2*>(&w.x);
    __half2 b = *reinterpret_cast<__half2*>(&w.y);
    float2 fa = __half22float2(a), fb = __half22float2(b);
    return make_float4(fa.x, fa.y, fb.x, fb.y);
}
__device__ __forceinline__ uint2 f4_to_h4(float4 v) {
    __half2 a = __floats2half2_rn(v.x, v.y);
    __half2 b = __floats2half2_rn(v.z, v.w);
    uint2 u;
    u.x = *reinterpret_cast<unsigned*>(&a);
    u.y = *reinterpret_cast<unsigned*>(&b);
    return u;
}
__device__ __forceinline__ void mma_f16(float* d, const unsigned int* a,
                                        unsigned int b0, unsigned int b1) {
    asm volatile(
        "mma.sync.aligned.m16n8k16.row.col.f32.f16.f16.f32 "
        "{%0,%1,%2,%3}, {%4,%5,%6,%7}, {%8,%9}, {%0,%1,%2,%3};"
        : "+f"(d[0]), "+f"(d[1]), "+f"(d[2]), "+f"(d[3])
        : "r"(a[0]), "r"(a[1]), "r"(a[2]), "r"(a[3]), "r"(b0), "r"(b1));
}
__device__ __forceinline__ void ldsm_x4(unsigned int* r, unsigned int addr) {
    asm volatile("ldmatrix.sync.aligned.m8n8.x4.shared.b16 {%0,%1,%2,%3}, [%4];"
        : "=r"(r[0]), "=r"(r[1]), "=r"(r[2]), "=r"(r[3]) : "r"(addr));
}

// ---------------- fused input projection + edge histogram ----------------
#define IP_BLOCKS 1024
#define HIST_BLOCKS 2048
__global__ __launch_bounds__(256) void k_inproj_hist(
    const float* __restrict__ inputs, const float* __restrict__ noise,
    const float* __restrict__ Win, const float* __restrict__ bin,
    const float* __restrict__ Wn, const float* __restrict__ bn,
    float* __restrict__ X, __half* __restrict__ Ah, float* __restrict__ stats,
    const int* __restrict__ L_rows, int* __restrict__ cnt)
{
    int tid = threadIdx.x;
    if (blockIdx.x >= IP_BLOCKS) {
        int stride = HIST_BLOCKS * 256;
        for (int t = (blockIdx.x - IP_BLOCKS) * 256 + tid; t < BB * EE; t += stride) {
            int b = t / EE;
            atomicAdd(&cnt[b * NN + L_rows[t]], 1);
        }
        return;
    }
    __shared__ float sU[8][104];
    int half = tid >> 7;
    int t128 = tid & 127;
    float bias = bin[t128] + bn[t128];
    float psum = 0.f, psq = 0.f;
    for (int base = blockIdx.x * 8; base < ROWS_TOT; base += IP_BLOCKS * 8) {
        __syncthreads();
        for (int idx = tid; idx < 8 * 103; idx += 256) {
            int r = idx / 103, k = idx - r * 103;
            int row = base + r;
            sU[r][k] = (k < 100) ? noise[(size_t)row * 100 + k]
                                 : inputs[(size_t)row * 3 + (k - 100)];
        }
        __syncthreads();
        int r0 = half * 4;
        float acc0 = bias, acc1 = bias, acc2 = bias, acc3 = bias;
        #pragma unroll 5
        for (int kq = 0; kq < 25; kq++) {
            int k = kq * 4;
            float w0 = __ldg(&Wn[(k + 0) * 128 + t128]);
            float w1 = __ldg(&Wn[(k + 1) * 128 + t128]);
            float w2 = __ldg(&Wn[(k + 2) * 128 + t128]);
            float w3 = __ldg(&Wn[(k + 3) * 128 + t128]);
            float4 u0 = *reinterpret_cast<const float4*>(&sU[r0 + 0][k]);
            float4 u1 = *reinterpret_cast<const float4*>(&sU[r0 + 1][k]);
            float4 u2 = *reinterpret_cast<const float4*>(&sU[r0 + 2][k]);
            float4 u3 = *reinterpret_cast<const float4*>(&sU[r0 + 3][k]);
            acc0 += u0.x * w0 + u0.y * w1 + u0.z * w2 + u0.w * w3;
            acc1 += u1.x * w0 + u1.y * w1 + u1.z * w2 + u1.w * w3;
            acc2 += u2.x * w0 + u2.y * w1 + u2.z * w2 + u2.w * w3;
            acc3 += u3.x * w0 + u3.y * w1 + u3.z * w2 + u3.w * w3;
        }
        #pragma unroll
        for (int k = 0; k < 3; k++) {
            float w = __ldg(&Win[k * 128 + t128]);
            acc0 += sU[r0 + 0][100 + k] * w;
            acc1 += sU[r0 + 1][100 + k] * w;
            acc2 += sU[r0 + 2][100 + k] * w;
            acc3 += sU[r0 + 3][100 + k] * w;
        }
        float accs[4] = {acc0, acc1, acc2, acc3};
        #pragma unroll
        for (int r = 0; r < 4; r++) {
            int row = base + r0 + r;
            float v = accs[r];
            X[(size_t)row * CC + t128] = v;
            float e = eluf(v);
            Ah[(size_t)row * CC + t128] = __float2half_rn(e);
            psum += e; psq += e * e;
        }
    }
    atomicAdd(&stats[t128], psum);
    atomicAdd(&stats[128 + t128], psq);
}

__global__ void k_scan(const int* __restrict__ cnt, int* rowptr, int* cursor) {
    __shared__ int sh[1024];
    int b = blockIdx.x, tid = threadIdx.x;
    const int CH = 49;
    int start = tid * CH;
    int end = min(start + CH, NN);
    int s = 0;
    for (int i = start; i < end; i++) s += cnt[b * NN + i];
    sh[tid] = s;
    __syncthreads();
    for (int off = 1; off < 1024; off <<= 1) {
        int t = (tid >= off) ? sh[tid - off] : 0;
        __syncthreads();
        sh[tid] += t;
        __syncthreads();
    }
    int run = (tid == 0) ? 0 : sh[tid - 1];
    for (int i = start; i < end; i++) {
        rowptr[b * (NN + 1) + i] = run;
        cursor[b * NN + i] = run;
        run += cnt[b * NN + i];
    }
    if (tid == 1023) rowptr[b * (NN + 1) + NN] = run;
}

__global__ void k_scatter(const int* __restrict__ L_rows, const int* __restrict__ L_cols,
                          const float* __restrict__ L_vals, int* cursor, int2* csr,
                          int* cnt) {
    int stride = gridDim.x * blockDim.x;
    int t0 = blockIdx.x * blockDim.x + threadIdx.x;
    for (int i = t0; i < ROWS_TOT; i += stride) cnt[i] = 0;
    for (int t = t0; t < BB * EE; t += stride) {
        int b = t / EE;
        int r = L_rows[t];
        int pos = atomicAdd(&cursor[b * NN + r], 1);
        int2 e; e.x = L_cols[t]; e.y = __float_as_int(L_vals[t]);
        csr[(size_t)b * EE + pos] = e;
    }
}

// ---------------- CSR SpMM: 1 row/warp, uint2 fp16 gather, MLP=4, 2 accumulators ----------------
__global__ __launch_bounds__(256, 5) void k_spmm(
    const uint2* __restrict__ Ah2, const int* __restrict__ rowptr,
    const int2* __restrict__ csr, uint2* __restrict__ LXh2, float* __restrict__ stats)
{
    __shared__ float s_sum[128], s_sq[128];
    int tid = threadIdx.x;
    if (tid < 128) { s_sum[tid] = 0.f; s_sq[tid] = 0.f; }
    __syncthreads();
    int warp = tid >> 5, lane = tid & 31;
    float4 psum = {0,0,0,0}, psq = {0,0,0,0};
    for (int g = blockIdx.x * 8 + warp; g < ROWS_TOT; g += gridDim.x * 8) {
        int b = g / NN;
        int i = g - b * NN;
        int p0 = rowptr[b * (NN + 1) + i];
        int p1 = rowptr[b * (NN + 1) + i + 1];
        const int2* ev = csr + (size_t)b * EE;
        const uint2* Ab = Ah2 + (size_t)b * NN * 32;
        float4 a0 = {0,0,0,0}, a1 = {0,0,0,0};
        int p = p0;
        for (; p + 4 <= p1; p += 4) {
            int2 e0 = __ldg(&ev[p + 0]);
            int2 e1 = __ldg(&ev[p + 1]);
            int2 e2 = __ldg(&ev[p + 2]);
            int2 e3 = __ldg(&ev[p + 3]);
            uint2 w0 = __ldg(Ab + (size_t)e0.x * 32 + lane);
            uint2 w1 = __ldg(Ab + (size_t)e1.x * 32 + lane);
            uint2 w2 = __ldg(Ab + (size_t)e2.x * 32 + lane);
            uint2 w3 = __ldg(Ab + (size_t)e3.x * 32 + lane);
            a0 = fma4(h4_to_f4(w0), __int_as_float(e0.y), a0);
            a1 = fma4(h4_to_f4(w1), __int_as_float(e1.y), a1);
            a0 = fma4(h4_to_f4(w2), __int_as_float(e2.y), a0);
            a1 = fma4(h4_to_f4(w3), __int_as_float(e3.y), a1);
        }
        for (; p < p1; p++) {
            int2 e = __ldg(&ev[p]);
            a0 = fma4(h4_to_f4(__ldg(Ab + (size_t)e.x * 32 + lane)), __int_as_float(e.y), a0);
        }
        float4 acc;
        acc.x = a0.x + a1.x;
        acc.y = a0.y + a1.y;
        acc.z = a0.z + a1.z;
        acc.w = a0.w + a1.w;
        LXh2[(size_t)g * 32 + lane] = f4_to_h4(acc);
        psum.x += acc.x; psum.y += acc.y; psum.z += acc.z; psum.w += acc.w;
        psq.x += acc.x*acc.x; psq.y += acc.y*acc.y; psq.z += acc.z*acc.z; psq.w += acc.w*acc.w;
    }
    int ch = lane * 4;
    atomicAdd(&s_sum[ch+0], psum.x); atomicAdd(&s_sum[ch+1], psum.y);
    atomicAdd(&s_sum[ch+2], psum.z); atomicAdd(&s_sum[ch+3], psum.w);
    atomicAdd(&s_sq[ch+0], psq.x); atomicAdd(&s_sq[ch+1], psq.y);
    atomicAdd(&s_sq[ch+2], psq.z); atomicAdd(&s_sq[ch+3], psq.w);
    __syncthreads();
    if (tid < 128) {
        atomicAdd(&stats[tid], s_sum[tid]);
        atomicAdd(&stats[128 + tid], s_sq[tid]);
    }
}

// ---------------- BN fold: 8 channels/block ----------------
__global__ __launch_bounds__(128) void k_fold(
    float* __restrict__ sa, float* __restrict__ sl,
    const float* __restrict__ gamma, const float* __restrict__ beta,
    const float* __restrict__ W, const float* __restrict__ b,
    unsigned int* __restrict__ Wh32, unsigned int* __restrict__ Wl32,
    float* __restrict__ Wf2, float* bfp)
{
    __shared__ float s_scale[8], s_shift[8];
    int bi = blockIdx.x;
    int tid = threadIdx.x;
    if (tid < 8) {
        int c = bi * 8 + tid;
        float sum, sq;
        if (c < 128) { sum = sa[c]; sq = sa[128 + c]; }
        else         { sum = sl[c - 128]; sq = sl[c]; }
        float m = sum * MINV;
        float var = sq * MINV - m * m;
        float r = rsqrtf(var + 1e-5f);
        float sc = gamma[c] * r;
        s_scale[tid] = sc;
        s_shift[tid] = beta[c] - m * sc;
        if (c < 128) { sa[c] = 0.f; sa[128 + c] = 0.f; }
        else         { sl[c - 128] = 0.f; sl[c] = 0.f; }
    }
    __syncthreads();
    float bias = (bi == 0) ? b[tid] : 0.f;
    #pragma unroll
    for (int j = 0; j < 8; j += 2) {
        int c0 = bi * 8 + j;
        float w0r = W[c0 * 128 + tid];
        float w1r = W[(c0 + 1) * 128 + tid];
        float w0 = w0r * s_scale[j];
        float w1 = w1r * s_scale[j + 1];
        bias += s_shift[j] * w0r + s_shift[j + 1] * w1r;
        if (Wh32) {
            __half h0 = __float2half_rn(w0);
            __half h1 = __float2half_rn(w1);
            float l0 = w0 - __half2float(h0);
            float l1 = w1 - __half2float(h1);
            __half2 hw = __halves2half2(h0, h1);
            __half2 lw = __floats2half2_rn(l0, l1);
            Wh32[tid * 128 + (c0 >> 1)] = *reinterpret_cast<unsigned int*>(&hw);
            Wl32[tid * 128 + (c0 >> 1)] = *reinterpret_cast<unsigned int*>(&lw);
        } else {
            Wf2[c0 * 128 + tid] = w0;
            Wf2[(c0 + 1) * 128 + tid] = w1;
        }
    }
    bfp[bi * 128 + tid] = bias;
}

// ---------------- main GEMM: fp16 MMA, ldmatrix fragment loads, 2 CTAs/SM ----------------
__global__ __launch_bounds__(256, 2) void k_gemm_mma(
    const uint4* __restrict__ Ahin, const uint4* __restrict__ LXh,
    const unsigned int* __restrict__ Wh32, const unsigned int* __restrict__ Wl32,
    const float* __restrict__ bfp, const float* __restrict__ res, int has_res,
    float* __restrict__ xout, int store_x,
    float* __restrict__ Aout, int store_a,
    __half2* __restrict__ Ahout, float* __restrict__ stats)
{
    extern __shared__ unsigned int sm[];
    unsigned int* sWh = sm;              // 8192 words: [n][o^sw], current kc half
    unsigned int* sWl = sm + 8192;
    unsigned int* sA  = sm + 16384;      // 8192: 128 rows x 64 kpairs
    float* sBias = (float*)(sm + 24576);

    int tid = threadIdx.x, warp = tid >> 5, lane = tid & 31;
    int wm = warp >> 2, wn = warp & 3;
    int g = lane >> 2, t2 = lane & 3;

    if (tid < 128) {
        float bsum = 0.f;
        #pragma unroll
        for (int j = 0; j < 32; j++) bsum += bfp[j * 128 + tid];
        sBias[tid] = bsum;
    }
    float stS[4][2], stQ[4][2];
    #pragma unroll
    for (int i = 0; i < 4; i++) { stS[i][0]=0.f; stS[i][1]=0.f; stQ[i][0]=0.f; stQ[i][1]=0.f; }

    // ldmatrix lane decomposition
    int mq = lane >> 3, rq = lane & 7;
    int swq = rq << 2;
    unsigned int sA_u  = (unsigned int)__cvta_generic_to_shared(sA);
    unsigned int sWh_u = (unsigned int)__cvta_generic_to_shared(sWh);
    unsigned int sWl_u = (unsigned int)__cvta_generic_to_shared(sWl);
    int segA = (mq >> 1) * 4;
    unsigned int aBase[4];
    #pragma unroll
    for (int mf = 0; mf < 4; mf++) {
        int rowA = wm * 64 + mf * 16 + (mq & 1) * 8 + rq;
        aBase[mf] = sA_u + (unsigned int)(rowA * 64) * 4u;
    }
    int segB = (mq & 1) * 4;
    unsigned int bOffN[2];
    #pragma unroll
    for (int pr = 0; pr < 2; pr++) {
        int n = wn * 32 + (pr * 2 + (mq >> 1)) * 8 + rq;
        bOffN[pr] = (unsigned int)(n * 64) * 4u;
    }

    for (int tile = blockIdx.x; tile < NTILES_MMA; tile += gridDim.x) {
        int rbase = tile * 128;
        float acc[4][4][4];
        #pragma unroll
        for (int mf = 0; mf < 4; mf++)
            #pragma unroll
            for (int nf = 0; nf < 4; nf++)
                #pragma unroll
                for (int q = 0; q < 4; q++) acc[mf][nf][q] = 0.f;

        #pragma unroll 1
        for (int kc = 0; kc < 2; kc++) {
            __syncthreads();
            const uint4* src = kc ? LXh : Ahin;
            for (int idx = tid; idx < 2048; idx += 256) {
                int r = idx >> 4, u4 = idx & 15;
                uint4 w = __ldg(src + (size_t)(rbase + r) * 16 + u4);
                int d = r * 64 + ((u4 * 4) ^ ((r & 7) << 2));
                *reinterpret_cast<uint4*>(sA + d) = w;
            }
            for (int idx = tid; idx < 2048; idx += 256) {
                int n = idx >> 4, q4 = idx & 15;
                int o0 = q4 * 4;
                int sw = (n & 7) << 2;
                int d = n * 64 + (o0 ^ sw);
                uint4 wh = __ldg(reinterpret_cast<const uint4*>(Wh32 + n * 128 + kc * 64 + o0));
                uint4 wl = __ldg(reinterpret_cast<const uint4*>(Wl32 + n * 128 + kc * 64 + o0));
                *reinterpret_cast<uint4*>(sWh + d) = wh;
                *reinterpret_cast<uint4*>(sWl + d) = wl;
            }
            __syncthreads();
            #pragma unroll 1
            for (int s = 0; s < 8; s++) {
                unsigned int colA = (unsigned int)(((s * 8 + segA) ^ swq) * 4);
                unsigned int colB = (unsigned int)(((s * 8 + segB) ^ swq) * 4);
                unsigned int af[4][4];
                #pragma unroll
                for (int mf = 0; mf < 4; mf++)
                    ldsm_x4(af[mf], aBase[mf] + colA);
                unsigned int bh[2][4], bl[2][4];
                ldsm_x4(bh[0], sWh_u + bOffN[0] + colB);
                ldsm_x4(bh[1], sWh_u + bOffN[1] + colB);
                #pragma unroll
                for (int pr = 0; pr < 2; pr++)
                    #pragma unroll
                    for (int nfi = 0; nfi < 2; nfi++) {
                        int nf = pr * 2 + nfi;
                        #pragma unroll
                        for (int mf = 0; mf < 4; mf++)
                            mma_f16(acc[mf][nf], af[mf], bh[pr][nfi * 2], bh[pr][nfi * 2 + 1]);
                    }
                ldsm_x4(bl[0], sWl_u + bOffN[0] + colB);
                ldsm_x4(bl[1], sWl_u + bOffN[1] + colB);
                #pragma unroll
                for (int pr = 0; pr < 2; pr++)
                    #pragma unroll
                    for (int nfi = 0; nfi < 2; nfi++) {
                        int nf = pr * 2 + nfi;
                        #pragma unroll
                        for (int mf = 0; mf < 4; mf++)
                            mma_f16(acc[mf][nf], af[mf], bl[pr][nfi * 2], bl[pr][nfi * 2 + 1]);
                    }
            }
        }
        // epilogue
        #pragma unroll
        for (int mf = 0; mf < 4; mf++) {
            int row0 = rbase + wm * 64 + mf * 16 + g;
            int row1 = row0 + 8;
            #pragma unroll
            for (int nf = 0; nf < 4; nf++) {
                int c0 = wn * 32 + nf * 8 + t2 * 2;
                float b0 = sBias[c0], b1 = sBias[c0 + 1];
                float x00 = acc[mf][nf][0] + b0, x01 = acc[mf][nf][1] + b1;
                float x10 = acc[mf][nf][2] + b0, x11 = acc[mf][nf][3] + b1;
                if (row0 < ROWS_TOT) {
                    if (has_res) {
                        float2 rv = *reinterpret_cast<const float2*>(res + (size_t)row0 * CC + c0);
                        x00 += rv.x; x01 += rv.y;
                    }
                    if (store_x) *reinterpret_cast<float2*>(xout + (size_t)row0 * CC + c0) = make_float2(x00, x01);
                    float e00 = eluf(x00), e01 = eluf(x01);
                    if (store_a) *reinterpret_cast<float2*>(Aout + (size_t)row0 * CC + c0) = make_float2(e00, e01);
                    Ahout[(size_t)row0 * 64 + (c0 >> 1)] = __floats2half2_rn(e00, e01);
                    stS[nf][0] += e00; stS[nf][1] += e01;
                    stQ[nf][0] += e00 * e00; stQ[nf][1] += e01 * e01;
                }
                if (row1 < ROWS_TOT) {
                    if (has_res) {
                        float2 rv = *reinterpret_cast<const float2*>(res + (size_t)row1 * CC + c0);
                        x10 += rv.x; x11 += rv.y;
                    }
                    if (store_x) *reinterpret_cast<float2*>(xout + (size_t)row1 * CC + c0) = make_float2(x10, x11);
                    float e10 = eluf(x10), e11 = eluf(x11);
                    if (store_a) *reinterpret_cast<float2*>(Aout + (size_t)row1 * CC + c0) = make_float2(e10, e11);
                    Ahout[(size_t)row1 * 64 + (c0 >> 1)] = __floats2half2_rn(e10, e11);
                    stS[nf][0] += e10; stS[nf][1] += e11;
                    stQ[nf][0] += e10 * e10; stQ[nf][1] += e11 * e11;
                }
            }
        }
    }
    #pragma unroll
    for (int nf = 0; nf < 4; nf++) {
        #pragma unroll
        for (int c = 0; c < 2; c++) {
            float s = stS[nf][c], q = stQ[nf][c];
            #pragma unroll
            for (int off = 4; off < 32; off <<= 1) {
                s += __shfl_xor_sync(0xFFFFFFFFu, s, off);
                q += __shfl_xor_sync(0xFFFFFFFFu, q, off);
            }
            if (g == 0) {
                int ch = wn * 32 + nf * 8 + t2 * 2 + c;
                atomicAdd(&stats[ch], s);
                atomicAdd(&stats[128 + ch], q);
            }
        }
    }
}

// ---------------- final head: 256 threads, __ldg weights, float4 broadcasts ----------------
#define FIN_BLOCKS 2048
__global__ __launch_bounds__(256) void k_final(
    const float* __restrict__ Ain, const float* __restrict__ Wf2,
    const float* __restrict__ bfp2, const float* __restrict__ Wmu,
    const float* __restrict__ bmu, const float* __restrict__ logvar,
    const float* __restrict__ inputs, float* __restrict__ out)
{
    __shared__ float sU[8][128];
    __shared__ float sWmu[128 * 3];
    __shared__ float sred[8][4][3];
    int tid = threadIdx.x;
    int half = tid >> 7;
    int t128 = tid & 127;
    int warp = tid >> 5, lane = tid & 31;
    for (int idx = tid; idx < 384; idx += 256) sWmu[idx] = Wmu[idx];
    float bias = 0.f;
    #pragma unroll
    for (int j = 0; j < 16; j++) bias += bfp2[j * 128 + t128];
    float lv = logvar[0];
    for (int base = blockIdx.x * 8; base < ROWS_TOT; base += FIN_BLOCKS * 8) {
        __syncthreads();
        for (int idx = tid; idx < 256; idx += 256) {
            int r = idx >> 5, q = idx & 31;
            st4(&sU[r][q * 4], ld4(Ain + (size_t)(base + r) * CC + q * 4));
        }
        __syncthreads();
        int r0 = half * 4;
        float acc0 = bias, acc1 = bias, acc2 = bias, acc3 = bias;
        #pragma unroll 8
        for (int kq = 0; kq < 32; kq++) {
            int k = kq * 4;
            float w0 = __ldg(&Wf2[(k + 0) * 128 + t128]);
            float w1 = __ldg(&Wf2[(k + 1) * 128 + t128]);
            float w2 = __ldg(&Wf2[(k + 2) * 128 + t128]);
            float w3 = __ldg(&Wf2[(k + 3) * 128 + t128]);
            float4 u0 = *reinterpret_cast<const float4*>(&sU[r0 + 0][k]);
            float4 u1 = *reinterpret_cast<const float4*>(&sU[r0 + 1][k]);
            float4 u2 = *reinterpret_cast<const float4*>(&sU[r0 + 2][k]);
            float4 u3 = *reinterpret_cast<const float4*>(&sU[r0 + 3][k]);
            acc0 += u0.x * w0 + u0.y * w1 + u0.z * w2 + u0.w * w3;
            acc1 += u1.x * w0 + u1.y * w1 + u1.z * w2 + u1.w * w3;
            acc2 += u2.x * w0 + u2.y * w1 + u2.z * w2 + u2.w * w3;
            acc3 += u3.x * w0 + u3.y * w1 + u3.z * w2 + u3.w * w3;
        }
        float wm0 = sWmu[t128 * 3 + 0], wm1 = sWmu[t128 * 3 + 1], wm2 = sWmu[t128 * 3 + 2];
        float accs[4] = {acc0, acc1, acc2, acc3};
        #pragma unroll
        for (int r = 0; r < 4; r++) {
            float z = eluf(accs[r]);
            float p0 = z * wm0, p1 = z * wm1, p2 = z * wm2;
            #pragma unroll
            for (int off = 16; off; off >>= 1) {
                p0 += __shfl_down_sync(0xFFFFFFFFu, p0, off);
                p1 += __shfl_down_sync(0xFFFFFFFFu, p1, off);
                p2 += __shfl_down_sync(0xFFFFFFFFu, p2, off);
            }
            if (lane == 0) { sred[warp][r][0] = p0; sred[warp][r][1] = p1; sred[warp][r][2] = p2; }
        }
        __syncthreads();
        if (tid < 24) {
            int r = tid / 3, j = tid - r * 3;
            int h = r >> 2, rl = r & 3;
            float m = sred[h * 4 + 0][rl][j] + sred[h * 4 + 1][rl][j]
                    + sred[h * 4 + 2][rl][j] + sred[h * 4 + 3][rl][j] + bmu[j];
            size_t row = base + r;
            out[row * 3 + j] = m + inputs[row * 3 + j];
            out[(size_t)ROWS_TOT * 3 + row * 3 + j] = lv;
        }
    }
}

extern "C" void kernel_launch(void* const* d_in, const int* in_sizes, int n_in,
                              void* d_out, int out_size)
{
    const float* inputs  = (const float*)d_in[0];
    const float* noise   = (const float*)d_in[1];
    const int*   L_rows  = (const int*)d_in[3];
    const int*   L_cols  = (const int*)d_in[4];
    const float* L_vals  = (const float*)d_in[5];
    const float* W_in    = (const float*)d_in[6];
    const float* b_in    = (const float*)d_in[7];
    const float* W_noise = (const float*)d_in[8];
    const float* b_noise = (const float*)d_in[9];
    const float* rn_gamma= (const float*)d_in[10];
    const float* rn_beta = (const float*)d_in[11];
    const float* rn_W    = (const float*)d_in[12];
    const float* rn_b    = (const float*)d_in[13];
    const float* bn2_g   = (const float*)d_in[14];
    const float* bn2_b   = (const float*)d_in[15];
    const float* W2      = (const float*)d_in[16];
    const float* b2      = (const float*)d_in[17];
    const float* W_mu    = (const float*)d_in[18];
    const float* b_mu    = (const float*)d_in[19];
    const float* logvar  = (const float*)d_in[20];
    float* out = (float*)d_out;

    float *X, *A, *sa, *sl, *bf, *Wf2, *bf2;
    unsigned int *Wh32, *Wl32;
    uint4 *Ah, *LXh;
    int2* csr;
    int *rowptr, *cnt, *cursor;
    cudaGetSymbolAddress((void**)&X, g_X);
    cudaGetSymbolAddress((void**)&A, g_A);
    cudaGetSymbolAddress((void**)&Ah, g_Ah);
    cudaGetSymbolAddress((void**)&LXh, g_LXh);
    cudaGetSymbolAddress((void**)&sa, g_stats_a);
    cudaGetSymbolAddress((void**)&sl, g_stats_l);
    cudaGetSymbolAddress((void**)&Wh32, g_Wh32);
    cudaGetSymbolAddress((void**)&Wl32, g_Wl32);
    cudaGetSymbolAddress((void**)&bf, g_bf);
    cudaGetSymbolAddress((void**)&Wf2, g_Wf2);
    cudaGetSymbolAddress((void**)&bf2, g_bf2);
    cudaGetSymbolAddress((void**)&csr, g_csr);
    cudaGetSymbolAddress((void**)&rowptr, g_rowptr);
    cudaGetSymbolAddress((void**)&cnt, g_cnt);
    cudaGetSymbolAddress((void**)&cursor, g_cursor);

    const int SMEM_GEMM = 24576 * 4 + 512;   // 98,816 B -> 2 CTAs/SM
    cudaFuncSetAttribute(k_gemm_mma, cudaFuncAttributeMaxDynamicSharedMemorySize, 100 * 1024);

    k_inproj_hist<<<IP_BLOCKS + HIST_BLOCKS, 256>>>(
        inputs, noise, W_in, b_in, W_noise, b_noise,
        X, (__half*)Ah, sa, L_rows, cnt);
    k_scan<<<4, 1024>>>(cnt, rowptr, cursor);
    k_scatter<<<4096, 256>>>(L_rows, L_cols, L_vals, cursor, csr, cnt);

    for (int s = 0; s < 10; s++) {
        k_spmm<<<4096, 256>>>((const uint2*)Ah, rowptr, csr, (uint2*)LXh, sl + s * 256);
        k_fold<<<32, 128>>>(sa + s * 256, sl + s * 256,
                            rn_gamma + s * 256, rn_beta + s * 256,
                            rn_W + (size_t)s * 256 * 128, rn_b + s * 128,
                            Wh32, Wl32, (float*)0, bf);
        int odd = s & 1;
        k_gemm_mma<<<296, 256, SMEM_GEMM>>>(
            Ah, LXh, Wh32, Wl32, bf,
            X, odd, X, odd, A, (s == 9),
            (__half2*)Ah, sa + (s + 1) * 256);
    }

    k_fold<<<16, 128>>>(sa + 10 * 256, sa + 10 * 256, bn2_g, bn2_b, W2, b2,
                        (unsigned int*)0, (unsigned int*)0, Wf2, bf2);
    k_final<<<FIN_BLOCKS, 256>>>(
        A, Wf2, bf2, W_mu, b_mu, logvar, inputs, out);
}